// round 16
// baseline (speedup 1.0000x reference)
#include <cuda_runtime.h>
#include <cuda_bf16.h>
#include <mma.h>
#include <math.h>
using namespace nvcuda;

#define Tsz 256
#define Hsz 256

__device__ float g_h1[(size_t)256*512];             // only t=255 rows [b][512]
__device__ float g_xp[(size_t)65536*768];
__device__ float g_h2f[256*256];
__device__ float g_h2b[256*256];
__device__ __nv_bfloat16 g_ab[(size_t)65536*1536];  // A' = [xh|xl|xh]
__device__ __nv_bfloat16 g_bb[(size_t)768*1536];    // B' = [Wh|Wh|Wl]

typedef unsigned long long u64;
__device__ __forceinline__ u64 ffma2(u64 a,u64 b,u64 c){u64 d;asm("fma.rn.f32x2 %0,%1,%2,%3;":"=l"(d):"l"(a),"l"(b),"l"(c));return d;}
__device__ __forceinline__ u64 dup2(float v){u64 d;asm("mov.b64 %0,{%1,%2};":"=l"(d):"f"(v),"f"(v));return d;}
__device__ __forceinline__ u64 pk2(float a,float b){u64 d;asm("mov.b64 %0,{%1,%2};":"=l"(d):"f"(a),"f"(b));return d;}
__device__ __forceinline__ float lo2(u64 v){return __uint_as_float((unsigned)v);}
__device__ __forceinline__ float hi2(u64 v){return __uint_as_float((unsigned)(v>>32));}
__device__ __forceinline__ float sigm(float v){return __fdividef(1.f,1.f+__expf(-v));}
__device__ __forceinline__ float tanhf_(float v){float e=__expf(2.f*v);return 1.f-__fdividef(2.f,e+1.f);}

__device__ __forceinline__ unsigned smaddr(const void* p){unsigned a;
    asm("{.reg .u64 t; cvta.to.shared.u64 t,%1; cvt.u32.u64 %0,t;}":"=r"(a):"l"(p));return a;}
__device__ __forceinline__ unsigned mapar(unsigned a,unsigned r){unsigned o;
    asm("mapa.shared::cluster.u32 %0,%1,%2;":"=r"(o):"r"(a),"r"(r));return o;}
__device__ __forceinline__ void stc64(unsigned a,u64 v){
    asm volatile("st.shared::cluster.b64 [%0],%1;"::"r"(a),"l"(v):"memory");}
__device__ __forceinline__ void cpa16(unsigned d,const void* s){
    asm volatile("cp.async.cg.shared.global [%0],[%1],16;"::"r"(d),"l"(s):"memory");}
#define CPCOMMIT() asm volatile("cp.async.commit_group;":::"memory")
#define CARRIVE() asm volatile("barrier.cluster.arrive.aligned;":::"memory")
#define CWAIT()   asm volatile("barrier.cluster.wait.aligned;":::"memory")
#define CSYNC()   do{CARRIVE();CWAIT();}while(0)

__device__ __forceinline__ void split_st(__nv_bfloat16* base,size_t m,int col,float a,float b){
    __nv_bfloat16 ha=__float2bfloat16(a), hb=__float2bfloat16(b);
    __nv_bfloat16 la=__float2bfloat16(a-__bfloat162float(ha));
    __nv_bfloat16 lb=__float2bfloat16(b-__bfloat162float(hb));
    __nv_bfloat162 hi2v; hi2v.x=ha; hi2v.y=hb;
    __nv_bfloat162 lo2v; lo2v.x=la; lo2v.y=lb;
    *(__nv_bfloat162*)&base[m*1536+col]     =hi2v;
    *(__nv_bfloat162*)&base[m*1536+512+col] =lo2v;
    *(__nv_bfloat162*)&base[m*1536+1024+col]=hi2v;
}

// ===== layer 0 scan (unchanged from R14) ===================================
__global__ void __launch_bounds__(256,1) __cluster_dims__(4,1,1) gru0(
    const float* __restrict__ x,const float* __restrict__ Wih0,
    const float* __restrict__ Whh0,const float* __restrict__ bih0,
    const float* __restrict__ bhh0)
{
    extern __shared__ __align__(16) unsigned char smraw[];
    ulonglong2* wrz=(ulonglong2*)smraw;
    u64* wn=(u64*)(smraw+131072);
    float* hs=(float*)(smraw+196608);
    unsigned q; asm("mov.u32 %0,%%cluster_ctarank;":"=r"(q));
    const int cid=blockIdx.x>>2;
    const int dir=cid>>4, bbase=(cid&15)*16;
    const int tid=threadIdx.x, w=tid>>5, lane=tid&31;
    const int jp=(lane&7)|((w&3)<<3);
    const int sg=(lane>>3)|((w>>2)<<2);
    const int j0=q*64+2*jp, j1=j0+1;

    const float* Whh=Whh0+(size_t)dir*768*256;
    for(int i=tid;i<8192;i+=256){
        int k=i>>5,p=i&31,jj=q*64+2*p;
        ulonglong2 rz;
        rz.x=pk2(Whh[(size_t)(0*256+jj)*256+k],Whh[(size_t)(0*256+jj+1)*256+k]);
        rz.y=pk2(Whh[(size_t)(1*256+jj)*256+k],Whh[(size_t)(1*256+jj+1)*256+k]);
        wrz[i]=rz;
        wn[i]=pk2(Whh[(size_t)(2*256+jj)*256+k],Whh[(size_t)(2*256+jj+1)*256+k]);
    }
    const float* Wih=Wih0+(size_t)dir*768*4;
    const float4 wxr0=*(const float4*)&Wih[(0*256+j0)*4], wxr1=*(const float4*)&Wih[(0*256+j1)*4];
    const float4 wxz0=*(const float4*)&Wih[(1*256+j0)*4], wxz1=*(const float4*)&Wih[(1*256+j1)*4];
    const float4 wxn0=*(const float4*)&Wih[(2*256+j0)*4], wxn1=*(const float4*)&Wih[(2*256+j1)*4];
    const float* bi=bih0+dir*768; const float* bh=bhh0+dir*768;
    const float cr0=bi[j0],cr1=bi[j1],cz0=bi[256+j0],cz1=bi[256+j1],cn0=bi[512+j0],cn1=bi[512+j1];
    const float br0=bh[j0],br1=bh[j1],bz0=bh[256+j0],bz1=bh[256+j1],bn0=bh[512+j0],bn1=bh[512+j1];

    for(int i=tid;i<8192;i+=256)hs[i]=0.f;
    unsigned hsa=smaddr(hs);
    unsigned peer[4];
    #pragma unroll
    for(int r=0;r<4;r++)peer[r]=mapar(hsa,r);
    __syncthreads();
    CSYNC();

    const int s0=2*sg, s1=s0+1;
    const int bg0=bbase+s0, bg1=bbase+s1;

    for(int s=0;s<Tsz;s++){
        const int t=dir?255-s:s;
        const int cur=s&1;
        const u64* hk=(const u64*)(hs+cur*4096);
        u64 aR0=0,aZ0=0,aN0=0,aR1=0,aZ1=0,aN1=0;
        #pragma unroll 8
        for(int k=0;k<256;k++){
            u64 h2=hk[k*8+sg];
            u64 hA=dup2(lo2(h2)),hB=dup2(hi2(h2));
            ulonglong2 rz=wrz[k*32+jp];
            u64 nn=wn[k*32+jp];
            aR0=ffma2(hA,rz.x,aR0); aZ0=ffma2(hA,rz.y,aZ0); aN0=ffma2(hA,nn,aN0);
            aR1=ffma2(hB,rz.x,aR1); aZ1=ffma2(hB,rz.y,aZ1); aN1=ffma2(hB,nn,aN1);
        }
        float4 xv0=((const float4*)x)[(size_t)bg0*256+t];
        float4 xv1=((const float4*)x)[(size_t)bg1*256+t];
        const float* hc=hs+cur*4096;
        float hp00=hc[j0*16+s0],hp01=hc[j1*16+s0];
        float hp10=hc[j0*16+s1],hp11=hc[j1*16+s1];

        float xr0=cr0+xv0.x*wxr0.x+xv0.y*wxr0.y+xv0.z*wxr0.z+xv0.w*wxr0.w;
        float xr1=cr1+xv0.x*wxr1.x+xv0.y*wxr1.y+xv0.z*wxr1.z+xv0.w*wxr1.w;
        float xz0=cz0+xv0.x*wxz0.x+xv0.y*wxz0.y+xv0.z*wxz0.z+xv0.w*wxz0.w;
        float xz1=cz1+xv0.x*wxz1.x+xv0.y*wxz1.y+xv0.z*wxz1.z+xv0.w*wxz1.w;
        float xn0=cn0+xv0.x*wxn0.x+xv0.y*wxn0.y+xv0.z*wxn0.z+xv0.w*wxn0.w;
        float xn1=cn1+xv0.x*wxn1.x+xv0.y*wxn1.y+xv0.z*wxn1.z+xv0.w*wxn1.w;
        float r0=sigm(xr0+lo2(aR0)+br0), r1=sigm(xr1+hi2(aR0)+br1);
        float z0=sigm(xz0+lo2(aZ0)+bz0), z1=sigm(xz1+hi2(aZ0)+bz1);
        float n0=tanhf_(xn0+r0*(lo2(aN0)+bn0)), n1=tanhf_(xn1+r1*(hi2(aN0)+bn1));
        float hA0=(1.f-z0)*n0+z0*hp00, hA1=(1.f-z1)*n1+z1*hp01;

        xr0=cr0+xv1.x*wxr0.x+xv1.y*wxr0.y+xv1.z*wxr0.z+xv1.w*wxr0.w;
        xr1=cr1+xv1.x*wxr1.x+xv1.y*wxr1.y+xv1.z*wxr1.z+xv1.w*wxr1.w;
        xz0=cz0+xv1.x*wxz0.x+xv1.y*wxz0.y+xv1.z*wxz0.z+xv1.w*wxz0.w;
        xz1=cz1+xv1.x*wxz1.x+xv1.y*wxz1.y+xv1.z*wxz1.z+xv1.w*wxz1.w;
        xn0=cn0+xv1.x*wxn0.x+xv1.y*wxn0.y+xv1.z*wxn0.z+xv1.w*wxn0.w;
        xn1=cn1+xv1.x*wxn1.x+xv1.y*wxn1.y+xv1.z*wxn1.z+xv1.w*wxn1.w;
        r0=sigm(xr0+lo2(aR1)+br0); r1=sigm(xr1+hi2(aR1)+br1);
        z0=sigm(xz0+lo2(aZ1)+bz0); z1=sigm(xz1+hi2(aZ1)+bz1);
        n0=tanhf_(xn0+r0*(lo2(aN1)+bn0)); n1=tanhf_(xn1+r1*(hi2(aN1)+bn1));
        float hB0=(1.f-z0)*n0+z0*hp10, hB1=(1.f-z1)*n1+z1*hp11;

        const unsigned nxtb=(unsigned)((cur^1)*16384);
        u64 pj0=pk2(hA0,hB0), pj1=pk2(hA1,hB1);
        #pragma unroll
        for(int r=0;r<4;r++){
            unsigned pb=peer[r]+nxtb;
            stc64(pb+(unsigned)(j0*16+s0)*4,pj0);
            stc64(pb+(unsigned)(j1*16+s0)*4,pj1);
        }
        CARRIVE();
        split_st(g_ab,(size_t)bg0*256+t,dir*256+j0,hA0,hA1);
        split_st(g_ab,(size_t)bg1*256+t,dir*256+j0,hB0,hB1);
        if(t==255){
            *(float2*)&g_h1[(size_t)bg0*512+dir*256+j0]=make_float2(hA0,hA1);
            *(float2*)&g_h1[(size_t)bg1*512+dir*256+j0]=make_float2(hB0,hB1);
        }
        if(s<Tsz-1)CWAIT();
    }
    CWAIT();
}

// ===== W conversion ========================================================
__global__ void convW(const float* __restrict__ Wih1){
    const int n=blockIdx.x, k=threadIdx.x;
    float w=Wih1[(size_t)n*512+k];
    __nv_bfloat16 hi=__float2bfloat16(w);
    __nv_bfloat16 lo=__float2bfloat16(w-__bfloat162float(hi));
    g_bb[(size_t)n*1536+k]=hi;
    g_bb[(size_t)n*1536+512+k]=hi;
    g_bb[(size_t)n*1536+1024+k]=lo;
}

// ===== xp GEMM via wmma bf16: k-chunk 64, 2-stage cp.async =================
#define LDM 72
__global__ void __launch_bounds__(256,2) xpw(){
    __shared__ __nv_bfloat16 As[2][128][LDM], Bs[2][128][LDM];
    const int bn=blockIdx.x, bm=blockIdx.y;
    const int tid=threadIdx.x, wid=tid>>5;
    const int wm=wid>>1, wnb=wid&1;
    wmma::fragment<wmma::accumulator,16,16,16,float> acc[2][4];
    #pragma unroll
    for(int i=0;i<2;i++)
        #pragma unroll
        for(int j=0;j<4;j++)wmma::fill_fragment(acc[i][j],0.f);

    const int lr=tid>>1, lh=(tid&1)*4;   // row 0..127, half-row of 4x16B
    #define LOADST(st,kc) do{ \
        _Pragma("unroll") \
        for(int u=0;u<4;u++) \
            cpa16(smaddr(&As[st][lr][(lh+u)*8]), &g_ab[(size_t)(bm*128+lr)*1536+(kc)*64+(lh+u)*8]); \
        _Pragma("unroll") \
        for(int u=0;u<4;u++) \
            cpa16(smaddr(&Bs[st][lr][(lh+u)*8]), &g_bb[(size_t)(bn*128+lr)*1536+(kc)*64+(lh+u)*8]); \
        CPCOMMIT(); }while(0)

    LOADST(0,0);
    for(int kc=0;kc<24;kc++){
        const int st=kc&1;
        if(kc<23){
            LOADST(st^1,kc+1);
            asm volatile("cp.async.wait_group 1;":::"memory");
        }else{
            asm volatile("cp.async.wait_group 0;":::"memory");
        }
        __syncthreads();
        #pragma unroll
        for(int kk=0;kk<4;kk++){
            wmma::fragment<wmma::matrix_a,16,16,16,__nv_bfloat16,wmma::row_major> af[2];
            wmma::fragment<wmma::matrix_b,16,16,16,__nv_bfloat16,wmma::col_major> bf[4];
            #pragma unroll
            for(int i=0;i<2;i++)wmma::load_matrix_sync(af[i],&As[st][wm*32+i*16][kk*16],LDM);
            #pragma unroll
            for(int j=0;j<4;j++)wmma::load_matrix_sync(bf[j],&Bs[st][wnb*64+j*16][kk*16],LDM);
            #pragma unroll
            for(int i=0;i<2;i++)
                #pragma unroll
                for(int j=0;j<4;j++)wmma::mma_sync(acc[i][j],af[i],bf[j],acc[i][j]);
        }
        __syncthreads();
    }
    #pragma unroll
    for(int i=0;i<2;i++)
        #pragma unroll
        for(int j=0;j<4;j++)
            wmma::store_matrix_sync(&g_xp[(size_t)(bm*128+wm*32+i*16)*768+bn*128+wnb*64+j*16],
                                    acc[i][j],768,wmma::mem_row_major);
}

// ===== layer 1 fwd scan: k-pair packed weights + h =========================
// ws: [128 k2][32 jp] x 48B {rz_k | rz_k1 | n_k,n_k1} = 192KB
// hs2: [2 buf][128 k2][8 sq][2 kk] u64 (pre-splatted) = 32KB
__global__ void __launch_bounds__(256,1) __cluster_dims__(4,1,1) gru1(
    const float* __restrict__ Whh1,const float* __restrict__ bih1,
    const float* __restrict__ bhh1)
{
    extern __shared__ __align__(16) unsigned char smraw[];
    u64* ws=(u64*)smraw;
    u64* hs2=(u64*)(smraw+196608);
    unsigned q; asm("mov.u32 %0,%%cluster_ctarank;":"=r"(q));
    const int cid=blockIdx.x>>2;
    const int tid=threadIdx.x, w=tid>>5, lane=tid&31;
    const int jp=(lane&7)|((w&3)<<3);
    const int sq=(lane>>3)|((w>>2)<<2);
    const int j0=q*64+2*jp, j1=j0+1;
    const int b=cid*8+sq;

    for(int i=tid;i<4096;i+=256){
        int k2=i>>5, p=i&31, k0=2*k2, jj=q*64+2*p;
        u64* sl=&ws[(size_t)i*6];
        sl[0]=pk2(Whh1[(size_t)(0*256+jj)*256+k0],  Whh1[(size_t)(0*256+jj+1)*256+k0]);
        sl[1]=pk2(Whh1[(size_t)(1*256+jj)*256+k0],  Whh1[(size_t)(1*256+jj+1)*256+k0]);
        sl[2]=pk2(Whh1[(size_t)(0*256+jj)*256+k0+1],Whh1[(size_t)(0*256+jj+1)*256+k0+1]);
        sl[3]=pk2(Whh1[(size_t)(1*256+jj)*256+k0+1],Whh1[(size_t)(1*256+jj+1)*256+k0+1]);
        sl[4]=pk2(Whh1[(size_t)(2*256+jj)*256+k0],  Whh1[(size_t)(2*256+jj+1)*256+k0]);
        sl[5]=pk2(Whh1[(size_t)(2*256+jj)*256+k0+1],Whh1[(size_t)(2*256+jj+1)*256+k0+1]);
    }
    const float cr0=bih1[j0]+bhh1[j0],         cr1=bih1[j1]+bhh1[j1];
    const float cz0=bih1[256+j0]+bhh1[256+j0], cz1=bih1[256+j1]+bhh1[256+j1];
    const float cx0=bih1[512+j0], cx1=bih1[512+j1];
    const float cn0=bhh1[512+j0], cn1=bhh1[512+j1];

    for(int i=tid;i<4096;i+=256)hs2[i]=0ull;
    unsigned hsa=smaddr(hs2);
    unsigned peer[4];
    #pragma unroll
    for(int r=0;r<4;r++)peer[r]=mapar(hsa,r);
    __syncthreads();
    CSYNC();

    const int wslot=(q*32+jp)*16+sq*2;   // own h target slot (u64 index)

    for(int t=0;t<Tsz;t++){
        const float* xr_=&g_xp[(size_t)(b*256+t)*768];
        float2 pr=__ldg((const float2*)(xr_+j0));
        float2 pz=__ldg((const float2*)(xr_+256+j0));
        float2 pn=__ldg((const float2*)(xr_+512+j0));

        const int cur=t&1;
        const u64* hk=hs2+cur*2048;
        u64 aR=0,aZ=0,aN=0;
        #pragma unroll 8
        for(int k2=0;k2<128;k2++){
            ulonglong2 hh=*(const ulonglong2*)&hk[k2*16+sq*2];
            const u64* sl=&ws[(size_t)(k2*32+jp)*6];
            ulonglong2 rzA=*(const ulonglong2*)sl;
            ulonglong2 rzB=*(const ulonglong2*)(sl+2);
            ulonglong2 nn=*(const ulonglong2*)(sl+4);
            aR=ffma2(hh.x,rzA.x,aR); aZ=ffma2(hh.x,rzA.y,aZ); aN=ffma2(hh.x,nn.x,aN);
            aR=ffma2(hh.y,rzB.x,aR); aZ=ffma2(hh.y,rzB.y,aZ); aN=ffma2(hh.y,nn.y,aN);
        }
        float hp0=lo2(hk[wslot]), hp1=lo2(hk[wslot+1]);
        float r0=sigm(pr.x+lo2(aR)+cr0), r1=sigm(pr.y+hi2(aR)+cr1);
        float z0=sigm(pz.x+lo2(aZ)+cz0), z1=sigm(pz.y+hi2(aZ)+cz1);
        float n0=tanhf_(pn.x+cx0+r0*(lo2(aN)+cn0));
        float n1=tanhf_(pn.y+cx1+r1*(hi2(aN)+cn1));
        float h0=(1.f-z0)*n0+z0*hp0, h1=(1.f-z1)*n1+z1*hp1;

        const unsigned nxtb=(unsigned)((cur^1)*16384);
        u64 s0=dup2(h0), s1=dup2(h1);
        #pragma unroll
        for(int r=0;r<4;r++){
            unsigned pb=peer[r]+nxtb+(unsigned)wslot*8;
            stc64(pb,s0);
            stc64(pb+8,s1);
        }
        CARRIVE();
        if(t==255)*(float2*)&g_h2f[b*256+j0]=make_float2(h0,h1);
        if(t<Tsz-1)CWAIT();
    }
    CWAIT();
}

// ===== layer 1 single bwd step (h=0): smem-staged weights ==================
__global__ void __launch_bounds__(256,1) g1bwd(
    const float* __restrict__ Wih1,const float* __restrict__ bih1,
    const float* __restrict__ bhh1)
{
    extern __shared__ __align__(16) u64 wsb[];   // [3][512][8 jp] = 98,304 B
    const int bt=blockIdx.x>>4, jt=blockIdx.x&15;
    const int tid=threadIdx.x;
    const float* W=Wih1+(size_t)768*512;

    for(int i=tid;i<3*512*8;i+=256){
        int p=i&7, k=(i>>3)&511, g=i>>12;
        int J0=jt*16+2*p;
        wsb[i]=pk2(W[(size_t)(g*256+J0)*512+k],W[(size_t)(g*256+J0+1)*512+k]);
    }
    __syncthreads();

    const int bl=tid>>3, jp=tid&7;
    const int b=bt*32+bl, j0=jt*16+2*jp, j1=j0+1;
    const float2* xp=(const float2*)&g_h1[(size_t)b*512];
    u64 ar=0,az=0,an=0;
    #pragma unroll 8
    for(int k2=0;k2<256;k2++){
        float2 xv=__ldg(&xp[k2]);
        u64 x0=dup2(xv.x),x1=dup2(xv.y);
        ar=ffma2(x0,wsb[(size_t)(0*512+2*k2  )*8+jp],ar);
        ar=ffma2(x1,wsb[(size_t)(0*512+2*k2+1)*8+jp],ar);
        az=ffma2(x0,wsb[(size_t)(1*512+2*k2  )*8+jp],az);
        az=ffma2(x1,wsb[(size_t)(1*512+2*k2+1)*8+jp],az);
        an=ffma2(x0,wsb[(size_t)(2*512+2*k2  )*8+jp],an);
        an=ffma2(x1,wsb[(size_t)(2*512+2*k2+1)*8+jp],an);
    }
    const float* bi=bih1+768; const float* bh=bhh1+768;
    float r0=sigm(lo2(ar)+bi[j0]+bh[j0]);
    float r1=sigm(hi2(ar)+bi[j1]+bh[j1]);
    float z0=sigm(lo2(az)+bi[256+j0]+bh[256+j0]);
    float z1=sigm(hi2(az)+bi[256+j1]+bh[256+j1]);
    float n0=tanhf_(lo2(an)+bi[512+j0]+r0*bh[512+j0]);
    float n1=tanhf_(hi2(an)+bi[512+j1]+r1*bh[512+j1]);
    *(float2*)&g_h2b[b*256+j0]=make_float2((1.f-z0)*n0,(1.f-z1)*n1);
}

// ===== head =====
__global__ void gru_head(const float* __restrict__ W_out,
                         const float* __restrict__ b_out,float* __restrict__ out){
    const int b=blockIdx.x, tid=threadIdx.x;
    float a0=0,a1=0,a2=0;
    for(int k=tid;k<Hsz;k+=128){
        float v=g_h2f[b*Hsz+k]+g_h2b[b*Hsz+k];
        a0+=v*W_out[k];a1+=v*W_out[256+k];a2+=v*W_out[512+k];
    }
    #pragma unroll
    for(int o=16;o>0;o>>=1){
        a0+=__shfl_xor_sync(0xffffffffu,a0,o);
        a1+=__shfl_xor_sync(0xffffffffu,a1,o);
        a2+=__shfl_xor_sync(0xffffffffu,a2,o);
    }
    __shared__ float red[3][4];
    if((tid&31)==0){int w=tid>>5;red[0][w]=a0;red[1][w]=a1;red[2][w]=a2;}
    __syncthreads();
    if(tid==0){
        a0=red[0][0]+red[0][1]+red[0][2]+red[0][3]+b_out[0];
        a1=red[1][0]+red[1][1]+red[1][2]+red[1][3]+b_out[1];
        a2=red[2][0]+red[2][1]+red[2][2]+red[2][3]+b_out[2];
        float m=fmaxf(a0,fmaxf(a1,a2));
        float e0=expf(a0-m),e1=expf(a1-m),e2=expf(a2-m);
        float inv=1.f/(e0+e1+e2);
        out[b*3+0]=e0*inv;out[b*3+1]=e1*inv;out[b*3+2]=e2*inv;
    }
}

extern "C" void kernel_launch(void* const* d_in,const int* in_sizes,int n_in,
                              void* d_out,int out_size){
    const float* x=(const float*)d_in[0];
    const float* Wih0=(const float*)d_in[1];
    const float* Whh0=(const float*)d_in[2];
    const float* bih0=(const float*)d_in[3];
    const float* bhh0=(const float*)d_in[4];
    const float* Wih1=(const float*)d_in[5];
    const float* Whh1=(const float*)d_in[6];
    const float* bih1=(const float*)d_in[7];
    const float* bhh1=(const float*)d_in[8];
    const float* W_out=(const float*)d_in[9];
    const float* b_out=(const float*)d_in[10];
    float* out=(float*)d_out;

    const int sm0=196608+32768;
    const int sm1=196608+32768;
    const int smb=98304;
    cudaFuncSetAttribute(gru0,cudaFuncAttributeMaxDynamicSharedMemorySize,sm0);
    cudaFuncSetAttribute(gru1,cudaFuncAttributeMaxDynamicSharedMemorySize,sm1);
    cudaFuncSetAttribute(g1bwd,cudaFuncAttributeMaxDynamicSharedMemorySize,smb);

    convW<<<768,512>>>(Wih1);
    gru0<<<128,256,sm0>>>(x,Wih0,Whh0,bih0,bhh0);
    xpw<<<dim3(6,512),256>>>();
    g1bwd<<<128,256,smb>>>(Wih1,bih1,bhh1);
    gru1<<<128,256,sm1>>>(Whh1,bih1,bhh1);
    gru_head<<<256,128>>>(W_out,b_out,out);
}

// round 17
// speedup vs baseline: 1.0968x; 1.0968x over previous
#include <cuda_runtime.h>
#include <cuda_bf16.h>
#include <mma.h>
#include <math.h>
using namespace nvcuda;

#define Tsz 256
#define Hsz 256

__device__ float g_h1[(size_t)256*512];             // only t=255 rows [b][512]
__device__ float g_xp[(size_t)65536*768];
__device__ float g_h2f[256*256];
__device__ float g_h2b[256*256];
__device__ __nv_bfloat16 g_ab[(size_t)65536*1536];  // A' = [xh|xl|xh]
__device__ __nv_bfloat16 g_bb[(size_t)768*1536];    // B' = [Wh|Wh|Wl]

typedef unsigned long long u64;
__device__ __forceinline__ u64 ffma2(u64 a,u64 b,u64 c){u64 d;asm("fma.rn.f32x2 %0,%1,%2,%3;":"=l"(d):"l"(a),"l"(b),"l"(c));return d;}
__device__ __forceinline__ u64 dup2(float v){u64 d;asm("mov.b64 %0,{%1,%2};":"=l"(d):"f"(v),"f"(v));return d;}
__device__ __forceinline__ u64 pk2(float a,float b){u64 d;asm("mov.b64 %0,{%1,%2};":"=l"(d):"f"(a),"f"(b));return d;}
__device__ __forceinline__ float lo2(u64 v){return __uint_as_float((unsigned)v);}
__device__ __forceinline__ float hi2(u64 v){return __uint_as_float((unsigned)(v>>32));}
__device__ __forceinline__ float sigm(float v){return __fdividef(1.f,1.f+__expf(-v));}
__device__ __forceinline__ float tanhf_(float v){float e=__expf(2.f*v);return 1.f-__fdividef(2.f,e+1.f);}

__device__ __forceinline__ unsigned smaddr(const void* p){unsigned a;
    asm("{.reg .u64 t; cvta.to.shared.u64 t,%1; cvt.u32.u64 %0,t;}":"=r"(a):"l"(p));return a;}
__device__ __forceinline__ unsigned mapar(unsigned a,unsigned r){unsigned o;
    asm("mapa.shared::cluster.u32 %0,%1,%2;":"=r"(o):"r"(a),"r"(r));return o;}
__device__ __forceinline__ void stc64(unsigned a,u64 v){
    asm volatile("st.shared::cluster.b64 [%0],%1;"::"r"(a),"l"(v):"memory");}
__device__ __forceinline__ void cpa16(unsigned d,const void* s){
    asm volatile("cp.async.cg.shared.global [%0],[%1],16;"::"r"(d),"l"(s):"memory");}
#define CPCOMMIT() asm volatile("cp.async.commit_group;":::"memory")
#define CARRIVE() asm volatile("barrier.cluster.arrive.aligned;":::"memory")
#define CWAIT()   asm volatile("barrier.cluster.wait.aligned;":::"memory")
#define CSYNC()   do{CARRIVE();CWAIT();}while(0)

__device__ __forceinline__ void split_st(__nv_bfloat16* base,size_t m,int col,float a,float b){
    __nv_bfloat16 ha=__float2bfloat16(a), hb=__float2bfloat16(b);
    __nv_bfloat16 la=__float2bfloat16(a-__bfloat162float(ha));
    __nv_bfloat16 lb=__float2bfloat16(b-__bfloat162float(hb));
    __nv_bfloat162 hi2v; hi2v.x=ha; hi2v.y=hb;
    __nv_bfloat162 lo2v; lo2v.x=la; lo2v.y=lb;
    *(__nv_bfloat162*)&base[m*1536+col]     =hi2v;
    *(__nv_bfloat162*)&base[m*1536+512+col] =lo2v;
    *(__nv_bfloat162*)&base[m*1536+1024+col]=hi2v;
}

// ===== layer 0 scan ========================================================
__global__ void __launch_bounds__(256,1) __cluster_dims__(4,1,1) gru0(
    const float* __restrict__ x,const float* __restrict__ Wih0,
    const float* __restrict__ Whh0,const float* __restrict__ bih0,
    const float* __restrict__ bhh0)
{
    extern __shared__ __align__(16) unsigned char smraw[];
    ulonglong2* wrz=(ulonglong2*)smraw;
    u64* wn=(u64*)(smraw+131072);
    float* hs=(float*)(smraw+196608);
    unsigned q; asm("mov.u32 %0,%%cluster_ctarank;":"=r"(q));
    const int cid=blockIdx.x>>2;
    const int dir=cid>>4, bbase=(cid&15)*16;
    const int tid=threadIdx.x, w=tid>>5, lane=tid&31;
    const int jp=(lane&7)|((w&3)<<3);
    const int sg=(lane>>3)|((w>>2)<<2);
    const int j0=q*64+2*jp, j1=j0+1;

    const float* Whh=Whh0+(size_t)dir*768*256;
    for(int i=tid;i<8192;i+=256){
        int k=i>>5,p=i&31,jj=q*64+2*p;
        ulonglong2 rz;
        rz.x=pk2(Whh[(size_t)(0*256+jj)*256+k],Whh[(size_t)(0*256+jj+1)*256+k]);
        rz.y=pk2(Whh[(size_t)(1*256+jj)*256+k],Whh[(size_t)(1*256+jj+1)*256+k]);
        wrz[i]=rz;
        wn[i]=pk2(Whh[(size_t)(2*256+jj)*256+k],Whh[(size_t)(2*256+jj+1)*256+k]);
    }
    const float* Wih=Wih0+(size_t)dir*768*4;
    const float4 wxr0=*(const float4*)&Wih[(0*256+j0)*4], wxr1=*(const float4*)&Wih[(0*256+j1)*4];
    const float4 wxz0=*(const float4*)&Wih[(1*256+j0)*4], wxz1=*(const float4*)&Wih[(1*256+j1)*4];
    const float4 wxn0=*(const float4*)&Wih[(2*256+j0)*4], wxn1=*(const float4*)&Wih[(2*256+j1)*4];
    const float* bi=bih0+dir*768; const float* bh=bhh0+dir*768;
    const float cr0=bi[j0],cr1=bi[j1],cz0=bi[256+j0],cz1=bi[256+j1],cn0=bi[512+j0],cn1=bi[512+j1];
    const float br0=bh[j0],br1=bh[j1],bz0=bh[256+j0],bz1=bh[256+j1],bn0=bh[512+j0],bn1=bh[512+j1];

    for(int i=tid;i<8192;i+=256)hs[i]=0.f;
    unsigned hsa=smaddr(hs);
    unsigned peer[4];
    #pragma unroll
    for(int r=0;r<4;r++)peer[r]=mapar(hsa,r);
    __syncthreads();
    CSYNC();

    const int s0=2*sg, s1=s0+1;
    const int bg0=bbase+s0, bg1=bbase+s1;

    for(int s=0;s<Tsz;s++){
        const int t=dir?255-s:s;
        const int cur=s&1;
        const u64* hk=(const u64*)(hs+cur*4096);
        u64 aR0=0,aZ0=0,aN0=0,aR1=0,aZ1=0,aN1=0;
        #pragma unroll 8
        for(int k=0;k<256;k++){
            u64 h2=hk[k*8+sg];
            u64 hA=dup2(lo2(h2)),hB=dup2(hi2(h2));
            ulonglong2 rz=wrz[k*32+jp];
            u64 nn=wn[k*32+jp];
            aR0=ffma2(hA,rz.x,aR0); aZ0=ffma2(hA,rz.y,aZ0); aN0=ffma2(hA,nn,aN0);
            aR1=ffma2(hB,rz.x,aR1); aZ1=ffma2(hB,rz.y,aZ1); aN1=ffma2(hB,nn,aN1);
        }
        float4 xv0=((const float4*)x)[(size_t)bg0*256+t];
        float4 xv1=((const float4*)x)[(size_t)bg1*256+t];
        const float* hc=hs+cur*4096;
        float hp00=hc[j0*16+s0],hp01=hc[j1*16+s0];
        float hp10=hc[j0*16+s1],hp11=hc[j1*16+s1];

        float xr0=cr0+xv0.x*wxr0.x+xv0.y*wxr0.y+xv0.z*wxr0.z+xv0.w*wxr0.w;
        float xr1=cr1+xv0.x*wxr1.x+xv0.y*wxr1.y+xv0.z*wxr1.z+xv0.w*wxr1.w;
        float xz0=cz0+xv0.x*wxz0.x+xv0.y*wxz0.y+xv0.z*wxz0.z+xv0.w*wxz0.w;
        float xz1=cz1+xv0.x*wxz1.x+xv0.y*wxz1.y+xv0.z*wxz1.z+xv0.w*wxz1.w;
        float xn0=cn0+xv0.x*wxn0.x+xv0.y*wxn0.y+xv0.z*wxn0.z+xv0.w*wxn0.w;
        float xn1=cn1+xv0.x*wxn1.x+xv0.y*wxn1.y+xv0.z*wxn1.z+xv0.w*wxn1.w;
        float r0=sigm(xr0+lo2(aR0)+br0), r1=sigm(xr1+hi2(aR0)+br1);
        float z0=sigm(xz0+lo2(aZ0)+bz0), z1=sigm(xz1+hi2(aZ0)+bz1);
        float n0=tanhf_(xn0+r0*(lo2(aN0)+bn0)), n1=tanhf_(xn1+r1*(hi2(aN0)+bn1));
        float hA0=(1.f-z0)*n0+z0*hp00, hA1=(1.f-z1)*n1+z1*hp01;

        xr0=cr0+xv1.x*wxr0.x+xv1.y*wxr0.y+xv1.z*wxr0.z+xv1.w*wxr0.w;
        xr1=cr1+xv1.x*wxr1.x+xv1.y*wxr1.y+xv1.z*wxr1.z+xv1.w*wxr1.w;
        xz0=cz0+xv1.x*wxz0.x+xv1.y*wxz0.y+xv1.z*wxz0.z+xv1.w*wxz0.w;
        xz1=cz1+xv1.x*wxz1.x+xv1.y*wxz1.y+xv1.z*wxz1.z+xv1.w*wxz1.w;
        xn0=cn0+xv1.x*wxn0.x+xv1.y*wxn0.y+xv1.z*wxn0.z+xv1.w*wxn0.w;
        xn1=cn1+xv1.x*wxn1.x+xv1.y*wxn1.y+xv1.z*wxn1.z+xv1.w*wxn1.w;
        r0=sigm(xr0+lo2(aR1)+br0); r1=sigm(xr1+hi2(aR1)+br1);
        z0=sigm(xz0+lo2(aZ1)+bz0); z1=sigm(xz1+hi2(aZ1)+bz1);
        n0=tanhf_(xn0+r0*(lo2(aN1)+bn0)); n1=tanhf_(xn1+r1*(hi2(aN1)+bn1));
        float hB0=(1.f-z0)*n0+z0*hp10, hB1=(1.f-z1)*n1+z1*hp11;

        const unsigned nxtb=(unsigned)((cur^1)*16384);
        u64 pj0=pk2(hA0,hB0), pj1=pk2(hA1,hB1);
        #pragma unroll
        for(int r=0;r<4;r++){
            unsigned pb=peer[r]+nxtb;
            stc64(pb+(unsigned)(j0*16+s0)*4,pj0);
            stc64(pb+(unsigned)(j1*16+s0)*4,pj1);
        }
        CARRIVE();
        split_st(g_ab,(size_t)bg0*256+t,dir*256+j0,hA0,hA1);
        split_st(g_ab,(size_t)bg1*256+t,dir*256+j0,hB0,hB1);
        if(t==255){
            *(float2*)&g_h1[(size_t)bg0*512+dir*256+j0]=make_float2(hA0,hA1);
            *(float2*)&g_h1[(size_t)bg1*512+dir*256+j0]=make_float2(hB0,hB1);
        }
        if(s<Tsz-1)CWAIT();
    }
    CWAIT();
}

// ===== W conversion ========================================================
__global__ void convW(const float* __restrict__ Wih1){
    const int n=blockIdx.x, k=threadIdx.x;
    float w=Wih1[(size_t)n*512+k];
    __nv_bfloat16 hi=__float2bfloat16(w);
    __nv_bfloat16 lo=__float2bfloat16(w-__bfloat162float(hi));
    g_bb[(size_t)n*1536+k]=hi;
    g_bb[(size_t)n*1536+512+k]=hi;
    g_bb[(size_t)n*1536+1024+k]=lo;
}

// ===== xp GEMM via wmma bf16 + 3-stage cp.async pipeline (R14 proven) ======
#define LDM 48
__global__ void __launch_bounds__(256,2) xpw(){
    __shared__ __nv_bfloat16 As[3][128][LDM], Bs[3][128][LDM];
    const int bn=blockIdx.x, bm=blockIdx.y;
    const int tid=threadIdx.x, wid=tid>>5;
    const int wm=wid>>1, wnb=wid&1;
    wmma::fragment<wmma::accumulator,16,16,16,float> acc[2][4];
    #pragma unroll
    for(int i=0;i<2;i++)
        #pragma unroll
        for(int j=0;j<4;j++)wmma::fill_fragment(acc[i][j],0.f);

    const int lr=tid>>2, lg=tid&3;
    #define LOADST(st,kc) do{ \
        cpa16(smaddr(&As[st][lr][lg*8]),      &g_ab[(size_t)(bm*128+lr)*1536+(kc)*32+lg*8]); \
        cpa16(smaddr(&As[st][64+lr][lg*8]),   &g_ab[(size_t)(bm*128+64+lr)*1536+(kc)*32+lg*8]); \
        cpa16(smaddr(&Bs[st][lr][lg*8]),      &g_bb[(size_t)(bn*128+lr)*1536+(kc)*32+lg*8]); \
        cpa16(smaddr(&Bs[st][64+lr][lg*8]),   &g_bb[(size_t)(bn*128+64+lr)*1536+(kc)*32+lg*8]); \
        CPCOMMIT(); }while(0)

    LOADST(0,0); LOADST(1,1);
    for(int kc=0;kc<48;kc++){
        const int st=kc%3;
        if(kc<46){
            LOADST((kc+2)%3,kc+2);
            asm volatile("cp.async.wait_group 2;":::"memory");
        }else if(kc==46){
            asm volatile("cp.async.wait_group 1;":::"memory");
        }else{
            asm volatile("cp.async.wait_group 0;":::"memory");
        }
        __syncthreads();
        #pragma unroll
        for(int kk=0;kk<2;kk++){
            wmma::fragment<wmma::matrix_a,16,16,16,__nv_bfloat16,wmma::row_major> af[2];
            wmma::fragment<wmma::matrix_b,16,16,16,__nv_bfloat16,wmma::col_major> bf[4];
            #pragma unroll
            for(int i=0;i<2;i++)wmma::load_matrix_sync(af[i],&As[st][wm*32+i*16][kk*16],LDM);
            #pragma unroll
            for(int j=0;j<4;j++)wmma::load_matrix_sync(bf[j],&Bs[st][wnb*64+j*16][kk*16],LDM);
            #pragma unroll
            for(int i=0;i<2;i++)
                #pragma unroll
                for(int j=0;j<4;j++)wmma::mma_sync(acc[i][j],af[i],bf[j],acc[i][j]);
        }
        __syncthreads();
    }
    #pragma unroll
    for(int i=0;i<2;i++)
        #pragma unroll
        for(int j=0;j<4;j++)
            wmma::store_matrix_sync(&g_xp[(size_t)(bm*128+wm*32+i*16)*768+bn*128+wnb*64+j*16],
                                    acc[i][j],768,wmma::mem_row_major);
}

// ===== layer 1 fwd scan (R14 layout; prefetch moved into barrier shadow) ===
__global__ void __launch_bounds__(256,1) __cluster_dims__(4,1,1) gru1(
    const float* __restrict__ Whh1,const float* __restrict__ bih1,
    const float* __restrict__ bhh1)
{
    extern __shared__ __align__(16) unsigned char smraw[];
    ulonglong2* wrz=(ulonglong2*)smraw;
    u64* wn=(u64*)(smraw+131072);
    u64* hs2=(u64*)(smraw+196608);
    unsigned q; asm("mov.u32 %0,%%cluster_ctarank;":"=r"(q));
    const int cid=blockIdx.x>>2;
    const int tid=threadIdx.x, w=tid>>5, lane=tid&31;
    const int jp=(lane&7)|((w&3)<<3);
    const int sq=(lane>>3)|((w>>2)<<2);
    const int j0=q*64+2*jp, j1=j0+1;
    const int b=cid*8+sq;

    for(int i=tid;i<8192;i+=256){
        int k=i>>5,p=i&31,jj=q*64+2*p;
        ulonglong2 rz;
        rz.x=pk2(Whh1[(size_t)(0*256+jj)*256+k],Whh1[(size_t)(0*256+jj+1)*256+k]);
        rz.y=pk2(Whh1[(size_t)(1*256+jj)*256+k],Whh1[(size_t)(1*256+jj+1)*256+k]);
        wrz[i]=rz;
        wn[i]=pk2(Whh1[(size_t)(2*256+jj)*256+k],Whh1[(size_t)(2*256+jj+1)*256+k]);
    }
    const float cr0=bih1[j0]+bhh1[j0],         cr1=bih1[j1]+bhh1[j1];
    const float cz0=bih1[256+j0]+bhh1[256+j0], cz1=bih1[256+j1]+bhh1[256+j1];
    const float cx0=bih1[512+j0], cx1=bih1[512+j1];
    const float cn0=bhh1[512+j0], cn1=bhh1[512+j1];

    for(int i=tid;i<4096;i+=256)hs2[i]=0ull;
    unsigned hsa=smaddr(hs2);
    unsigned peer[4];
    #pragma unroll
    for(int r=0;r<4;r++)peer[r]=mapar(hsa,r);
    __syncthreads();
    CSYNC();

    // prefetch t=0 gate rows
    const float* xr0_=&g_xp[(size_t)(b*256+0)*768];
    float2 pr=__ldg((const float2*)(xr0_+j0));
    float2 pz=__ldg((const float2*)(xr0_+256+j0));
    float2 pn=__ldg((const float2*)(xr0_+512+j0));

    for(int t=0;t<Tsz;t++){
        const int cur=t&1;
        const u64* hk=hs2+cur*2048;
        u64 aR=0,aZ=0,aN=0;
        #pragma unroll 8
        for(int k=0;k<256;k++){
            u64 hv=hk[k*8+sq];
            ulonglong2 rz=wrz[k*32+jp];
            aR=ffma2(hv,rz.x,aR); aZ=ffma2(hv,rz.y,aZ); aN=ffma2(hv,wn[k*32+jp],aN);
        }
        float hp0=lo2(hk[j0*8+sq]), hp1=lo2(hk[j1*8+sq]);
        float r0=sigm(pr.x+lo2(aR)+cr0), r1=sigm(pr.y+hi2(aR)+cr1);
        float z0=sigm(pz.x+lo2(aZ)+cz0), z1=sigm(pz.y+hi2(aZ)+cz1);
        float n0=tanhf_(pn.x+cx0+r0*(lo2(aN)+cn0));
        float n1=tanhf_(pn.y+cx1+r1*(hi2(aN)+cn1));
        float h0=(1.f-z0)*n0+z0*hp0, h1=(1.f-z1)*n1+z1*hp1;

        const unsigned nxtb=(unsigned)((cur^1)*16384);
        u64 s0=dup2(h0), s1=dup2(h1);
        #pragma unroll
        for(int r=0;r<4;r++){
            unsigned pb=peer[r]+nxtb;
            stc64(pb+(unsigned)(j0*8+sq)*8,s0);
            stc64(pb+(unsigned)(j1*8+sq)*8,s1);
        }
        CARRIVE();
        if(t<Tsz-1){
            // prefetch next step's gate rows in the barrier shadow
            const float* xr_=&g_xp[(size_t)(b*256+t+1)*768];
            pr=__ldg((const float2*)(xr_+j0));
            pz=__ldg((const float2*)(xr_+256+j0));
            pn=__ldg((const float2*)(xr_+512+j0));
            CWAIT();
        }else{
            *(float2*)&g_h2f[b*256+j0]=make_float2(h0,h1);
        }
    }
    CWAIT();
}

// ===== layer 1 single bwd step (h=0): smem-staged weights ==================
__global__ void __launch_bounds__(256,1) g1bwd(
    const float* __restrict__ Wih1,const float* __restrict__ bih1,
    const float* __restrict__ bhh1)
{
    extern __shared__ __align__(16) u64 wsb[];   // [3][512][8 jp] = 98,304 B
    const int bt=blockIdx.x>>4, jt=blockIdx.x&15;
    const int tid=threadIdx.x;
    const float* W=Wih1+(size_t)768*512;

    for(int i=tid;i<3*512*8;i+=256){
        int p=i&7, k=(i>>3)&511, g=i>>12;
        int J0=jt*16+2*p;
        wsb[i]=pk2(W[(size_t)(g*256+J0)*512+k],W[(size_t)(g*256+J0+1)*512+k]);
    }
    __syncthreads();

    const int bl=tid>>3, jp=tid&7;
    const int b=bt*32+bl, j0=jt*16+2*jp, j1=j0+1;
    const float2* xp=(const float2*)&g_h1[(size_t)b*512];
    u64 ar=0,az=0,an=0;
    #pragma unroll 8
    for(int k2=0;k2<256;k2++){
        float2 xv=__ldg(&xp[k2]);
        u64 x0=dup2(xv.x),x1=dup2(xv.y);
        ar=ffma2(x0,wsb[(size_t)(0*512+2*k2  )*8+jp],ar);
        ar=ffma2(x1,wsb[(size_t)(0*512+2*k2+1)*8+jp],ar);
        az=ffma2(x0,wsb[(size_t)(1*512+2*k2  )*8+jp],az);
        az=ffma2(x1,wsb[(size_t)(1*512+2*k2+1)*8+jp],az);
        an=ffma2(x0,wsb[(size_t)(2*512+2*k2  )*8+jp],an);
        an=ffma2(x1,wsb[(size_t)(2*512+2*k2+1)*8+jp],an);
    }
    const float* bi=bih1+768; const float* bh=bhh1+768;
    float r0=sigm(lo2(ar)+bi[j0]+bh[j0]);
    float r1=sigm(hi2(ar)+bi[j1]+bh[j1]);
    float z0=sigm(lo2(az)+bi[256+j0]+bh[256+j0]);
    float z1=sigm(hi2(az)+bi[256+j1]+bh[256+j1]);
    float n0=tanhf_(lo2(an)+bi[512+j0]+r0*bh[512+j0]);
    float n1=tanhf_(hi2(an)+bi[512+j1]+r1*bh[512+j1]);
    *(float2*)&g_h2b[b*256+j0]=make_float2((1.f-z0)*n0,(1.f-z1)*n1);
}

// ===== head =====
__global__ void gru_head(const float* __restrict__ W_out,
                         const float* __restrict__ b_out,float* __restrict__ out){
    const int b=blockIdx.x, tid=threadIdx.x;
    float a0=0,a1=0,a2=0;
    for(int k=tid;k<Hsz;k+=128){
        float v=g_h2f[b*Hsz+k]+g_h2b[b*Hsz+k];
        a0+=v*W_out[k];a1+=v*W_out[256+k];a2+=v*W_out[512+k];
    }
    #pragma unroll
    for(int o=16;o>0;o>>=1){
        a0+=__shfl_xor_sync(0xffffffffu,a0,o);
        a1+=__shfl_xor_sync(0xffffffffu,a1,o);
        a2+=__shfl_xor_sync(0xffffffffu,a2,o);
    }
    __shared__ float red[3][4];
    if((tid&31)==0){int w=tid>>5;red[0][w]=a0;red[1][w]=a1;red[2][w]=a2;}
    __syncthreads();
    if(tid==0){
        a0=red[0][0]+red[0][1]+red[0][2]+red[0][3]+b_out[0];
        a1=red[1][0]+red[1][1]+red[1][2]+red[1][3]+b_out[1];
        a2=red[2][0]+red[2][1]+red[2][2]+red[2][3]+b_out[2];
        float m=fmaxf(a0,fmaxf(a1,a2));
        float e0=expf(a0-m),e1=expf(a1-m),e2=expf(a2-m);
        float inv=1.f/(e0+e1+e2);
        out[b*3+0]=e0*inv;out[b*3+1]=e1*inv;out[b*3+2]=e2*inv;
    }
}

extern "C" void kernel_launch(void* const* d_in,const int* in_sizes,int n_in,
                              void* d_out,int out_size){
    const float* x=(const float*)d_in[0];
    const float* Wih0=(const float*)d_in[1];
    const float* Whh0=(const float*)d_in[2];
    const float* bih0=(const float*)d_in[3];
    const float* bhh0=(const float*)d_in[4];
    const float* Wih1=(const float*)d_in[5];
    const float* Whh1=(const float*)d_in[6];
    const float* bih1=(const float*)d_in[7];
    const float* bhh1=(const float*)d_in[8];
    const float* W_out=(const float*)d_in[9];
    const float* b_out=(const float*)d_in[10];
    float* out=(float*)d_out;

    const int sm0=196608+32768;
    const int sm1=196608+32768;
    const int smb=98304;
    cudaFuncSetAttribute(gru0,cudaFuncAttributeMaxDynamicSharedMemorySize,sm0);
    cudaFuncSetAttribute(gru1,cudaFuncAttributeMaxDynamicSharedMemorySize,sm1);
    cudaFuncSetAttribute(g1bwd,cudaFuncAttributeMaxDynamicSharedMemorySize,smb);

    convW<<<768,512>>>(Wih1);
    gru0<<<128,256,sm0>>>(x,Wih0,Whh0,bih0,bhh0);
    xpw<<<dim3(6,512),256>>>();
    g1bwd<<<128,256,smb>>>(Wih1,bih1,bhh1);
    gru1<<<128,256,sm1>>>(Whh1,bih1,bhh1);
    gru_head<<<256,128>>>(W_out,b_out,out);
}